// round 13
// baseline (speedup 1.0000x reference)
#include <cuda_runtime.h>
#include <cstdint>
#include <cstddef>

#define IN_F    4096
#define OUT_F   4096
#define BATCHSZ 16384
// stage1 per kb: M=16384, N=192, K=1024 ; stage2 per lb: M=16384, N=1024 (4x256), K=192

// scratch[(b*4 + l)*192 + kb*48 + b1], tf32-rounded fp32 (low 13 bits zero)
__device__ float g_scratch[(size_t)BATCHSZ * 4 * 192];
__device__ float g_w1r[4 * 192 * 1024];   // rna(tf32)-rounded weights
__device__ float g_w2r[4 * 1024 * 192];

#define SSTR 36   // padded row stride in 4B words

__device__ __forceinline__ uint32_t f2tf32(float f) {
    uint32_t r; asm("cvt.rna.tf32.f32 %0, %1;" : "=r"(r) : "f"(f)); return r;
}
#define CP16(dst, src) asm volatile("cp.async.cg.shared.global [%0], [%1], 16;" :: "r"(dst), "l"(src))
#define CPCOMMIT()     asm volatile("cp.async.commit_group;" ::: "memory")
#define CPWAIT(n)      asm volatile("cp.async.wait_group %0;" :: "n"(n) : "memory")

__device__ __forceinline__ uint32_t smem_u32(const void* p) {
    uint32_t a;
    asm("{ .reg .u64 t; cvta.to.shared.u64 t, %1; cvt.u32.u64 %0, t; }" : "=r"(a) : "l"(p));
    return a;
}

__device__ __forceinline__ void mma_tf32(float c[4], const uint32_t a[4], const uint32_t b[2]) {
    asm volatile(
        "mma.sync.aligned.m16n8k8.row.col.f32.tf32.tf32.f32 "
        "{%0,%1,%2,%3}, {%4,%5,%6,%7}, {%8,%9}, {%0,%1,%2,%3};"
        : "+f"(c[0]), "+f"(c[1]), "+f"(c[2]), "+f"(c[3])
        : "r"(a[0]), "r"(a[1]), "r"(a[2]), "r"(a[3]), "r"(b[0]), "r"(b[1]));
}

// ------------------------------------------------------------- prep
__global__ void prep_kernel(const float* __restrict__ w1, const float* __restrict__ w2) {
    const int n = 4 * 192 * 1024;
    for (int i = blockIdx.x * blockDim.x + threadIdx.x; i < n; i += gridDim.x * blockDim.x) {
        g_w1r[i] = __uint_as_float(f2tf32(w1[i]));
        g_w2r[i] = __uint_as_float(f2tf32(w2[i]));
    }
}

// ---------------------------------------------------------------------------
// Stage 1: CTA 64x192, K=1024 (32 chunks of 32). 384 thr = 12 warps.
// Warps 0-7: MMA 2m x 4slots(40 cols) covering cols 0..159, warp tile 32x40.
// Warps 8-11: FFMA, cols 160..191, each warp 16 rows x 32 cols (16 acc/thr).
// smem/stage (u32): A 64*36=2304 raw x ; B 192*36=6912 tf32 w1 -> 9216
// ---------------------------------------------------------------------------
#define S1_STW   9216
#define S1_AW    2304
#define S1_SMEM  (4 * S1_STW * 4)    // 147456 B

__global__ void __launch_bounds__(384, 1)
s1_kernel(const float* __restrict__ x)
{
    extern __shared__ uint32_t smu[];
    const uint32_t sb = smem_u32(smu);
    const int tid = threadIdx.x, wid = tid >> 5, lane = tid & 31;
    const int mblk = blockIdx.x, kb = blockIdx.y;
    const size_t m0 = (size_t)mblk * 64;

    const float* xA = x + m0 * IN_F + (size_t)kb * 1024;
    const float* wB = g_w1r + (size_t)kb * 192 * 1024;

    auto cpA = [&](int kc, int s) {
        const float* src = xA + kc * 32;
        const uint32_t dst = sb + (uint32_t)(s * S1_STW) * 4;
#pragma unroll
        for (int i = 0; i < 2; i++) {
            int idx = i * 384 + tid;
            if (idx < 512) {
                int row = idx >> 3, c4 = idx & 7;
                CP16(dst + (uint32_t)(row * SSTR + c4 * 4) * 4, src + (size_t)row * IN_F + c4 * 4);
            }
        }
    };
    auto cpB = [&](int kc, int s) {
        const float* src = wB + kc * 32;
        const uint32_t dst = sb + (uint32_t)(s * S1_STW + S1_AW) * 4;
#pragma unroll
        for (int i = 0; i < 4; i++) {
            int idx = i * 384 + tid, row = idx >> 3, c4 = idx & 7;
            CP16(dst + (uint32_t)(row * SSTR + c4 * 4) * 4, src + (size_t)row * 1024 + c4 * 4);
        }
    };

    // role params
    const int wm = (wid >> 2) & 1, slot = wid & 3;      // MMA warps 0-7
    const int lr = lane >> 2, lc = lane & 3;
    const int fw = wid - 8, tr = lane >> 3, tc = lane & 7;  // FFMA warps 8-11

    float c[2][5][4];
    float cf[4][4];
#pragma unroll
    for (int mi = 0; mi < 2; mi++)
#pragma unroll
        for (int ni = 0; ni < 5; ni++)
#pragma unroll
            for (int e = 0; e < 4; e++) c[mi][ni][e] = 0.f;
#pragma unroll
    for (int j = 0; j < 4; j++)
#pragma unroll
        for (int i = 0; i < 4; i++) cf[j][i] = 0.f;

    cpA(0, 0); cpB(0, 0); CPCOMMIT();
    cpA(1, 1); cpB(1, 1); CPCOMMIT();

#pragma unroll 1
    for (int kc = 0; kc < 32; kc++) {
        if (kc + 2 < 32) {
            cpA(kc + 2, (kc + 2) & 3); cpB(kc + 2, (kc + 2) & 3); CPCOMMIT();
            CPWAIT(2);
        } else if (kc + 2 == 32) {
            CPWAIT(1);
        } else {
            CPWAIT(0);
        }
        __syncthreads();

        const uint32_t* As = smu + (kc & 3) * S1_STW;
        const uint32_t* Bs = As + S1_AW;

        if (wid < 8) {
#pragma unroll
            for (int kk = 0; kk < 4; kk++) {
                const int cc = kk * 8 + lc;
                uint32_t a[2][4], b[5][2];
#pragma unroll
                for (int mi = 0; mi < 2; mi++) {
                    int r = wm * 32 + mi * 16 + lr;
                    a[mi][0] = f2tf32(__uint_as_float(As[r * SSTR + cc]));
                    a[mi][1] = f2tf32(__uint_as_float(As[(r + 8) * SSTR + cc]));
                    a[mi][2] = f2tf32(__uint_as_float(As[r * SSTR + cc + 4]));
                    a[mi][3] = f2tf32(__uint_as_float(As[(r + 8) * SSTR + cc + 4]));
                }
#pragma unroll
                for (int ni = 0; ni < 5; ni++) {
                    int n = slot * 40 + ni * 8 + lr;
                    b[ni][0] = Bs[n * SSTR + cc];
                    b[ni][1] = Bs[n * SSTR + cc + 4];
                }
#pragma unroll
                for (int mi = 0; mi < 2; mi++)
#pragma unroll
                    for (int ni = 0; ni < 5; ni++)
                        mma_tf32(c[mi][ni], a[mi], b[ni]);
            }
        } else {
            const float* Af = (const float*)As;
            const float* Bf = (const float*)Bs;
            const int r0 = 16 * fw + tr;
            const int n0 = 160 + tc;
#pragma unroll 8
            for (int k = 0; k < 32; k++) {
                float av[4], bv[4];
#pragma unroll
                for (int j = 0; j < 4; j++) av[j] = Af[(r0 + 4 * j) * SSTR + k];
#pragma unroll
                for (int i = 0; i < 4; i++) bv[i] = Bf[(n0 + 8 * i) * SSTR + k];
#pragma unroll
                for (int j = 0; j < 4; j++)
#pragma unroll
                    for (int i = 0; i < 4; i++) cf[j][i] += av[j] * bv[i];
            }
        }
    }

    // Epilogues: tf32-round, fused block transpose into scratch.
    if (wid < 8) {
#pragma unroll
        for (int mi = 0; mi < 2; mi++) {
            int row0 = wm * 32 + mi * 16 + lr;
#pragma unroll
            for (int ni = 0; ni < 5; ni++) {
                int q = slot * 40 + ni * 8 + 2 * lc;   // even; pair never straddles l
                int l = q / 48, b1 = q % 48;
                size_t g0 = ((m0 + row0) * 4 + l) * 192 + (size_t)kb * 48 + b1;
                float2 v0 = {__uint_as_float(f2tf32(c[mi][ni][0])),
                             __uint_as_float(f2tf32(c[mi][ni][1]))};
                float2 v1 = {__uint_as_float(f2tf32(c[mi][ni][2])),
                             __uint_as_float(f2tf32(c[mi][ni][3]))};
                *(float2*)(g_scratch + g0) = v0;
                *(float2*)(g_scratch + g0 + (size_t)8 * 4 * 192) = v1;
            }
        }
    } else {
#pragma unroll
        for (int j = 0; j < 4; j++) {
            int row = 16 * fw + tr + 4 * j;
#pragma unroll
            for (int i = 0; i < 4; i++) {
                int q = 160 + tc + 8 * i;              // all in l=3
                size_t g0 = ((m0 + row) * 4 + 3) * 192 + (size_t)kb * 48 + (q - 144);
                g_scratch[g0] = __uint_as_float(f2tf32(cf[j][i]));
            }
        }
    }
}

// ---------------------------------------------------------------------------
// Stage 2: CTA 64x256, K=192 (6 chunks of 32). 384 thr = 12 warps.
// Warps 0-7: MMA 2m x 4 slots {56,48,56,48} @ {0,56,104,160} (cols 0..207),
//            slot = wm ? (wid&3)^1 : (wid&3)  -> each SMSP gets one 7ni+one 6ni.
// Warps 8-11: FFMA cols 208..255, each warp 16 rows x 48 cols (24 acc/thr).
// smem/stage (u32): A 64*36=2304 ; B 256*36=9216 -> 11520
// ---------------------------------------------------------------------------
#define S2_STW   11520
#define S2_AW    2304
#define S2_SMEM  (4 * S2_STW * 4)    // 184320 B

template<int NI>
__device__ __forceinline__ void s2_mma_chunk(const uint32_t* As, const uint32_t* Bs,
                                             float (&c)[2][7][4],
                                             int wm, int noff, int lr, int lc)
{
#pragma unroll
    for (int kk = 0; kk < 4; kk++) {
        const int cc = kk * 8 + lc;
        uint32_t a[2][4], b[NI][2];
#pragma unroll
        for (int mi = 0; mi < 2; mi++) {
            int r = wm * 32 + mi * 16 + lr;
            a[mi][0] = As[r * SSTR + cc];
            a[mi][1] = As[(r + 8) * SSTR + cc];
            a[mi][2] = As[r * SSTR + cc + 4];
            a[mi][3] = As[(r + 8) * SSTR + cc + 4];
        }
#pragma unroll
        for (int ni = 0; ni < NI; ni++) {
            int n = noff + ni * 8 + lr;
            b[ni][0] = Bs[n * SSTR + cc];
            b[ni][1] = Bs[n * SSTR + cc + 4];
        }
#pragma unroll
        for (int mi = 0; mi < 2; mi++)
#pragma unroll
            for (int ni = 0; ni < NI; ni++)
                mma_tf32(c[mi][ni], a[mi], b[ni]);
    }
}

template<int NI>
__device__ __forceinline__ void s2_mma_epi(float (&c)[2][7][4], float* out,
                                           const float* bias, size_t m0,
                                           int gcolbase, int wm, int noff,
                                           int lr, int lc)
{
#pragma unroll
    for (int mi = 0; mi < 2; mi++) {
        int row0 = wm * 32 + mi * 16 + lr;
#pragma unroll
        for (int ni = 0; ni < NI; ni++) {
            int gcol = gcolbase + noff + ni * 8 + 2 * lc;
            float2 bsv = *(const float2*)(bias + gcol);
            float* o0 = out + (m0 + row0) * OUT_F + gcol;
            float2 v0 = {c[mi][ni][0] + bsv.x, c[mi][ni][1] + bsv.y};
            float2 v1 = {c[mi][ni][2] + bsv.x, c[mi][ni][3] + bsv.y};
            *(float2*)o0 = v0;
            *(float2*)(o0 + (size_t)8 * OUT_F) = v1;
        }
    }
}

__global__ void __launch_bounds__(384, 1)
s2_kernel(const float* __restrict__ bias, float* __restrict__ out)
{
    extern __shared__ uint32_t smu[];
    const uint32_t sb = smem_u32(smu);
    const int tid = threadIdx.x, wid = tid >> 5, lane = tid & 31;
    const int nblk = blockIdx.x, mblk = blockIdx.y, lb = blockIdx.z;
    const size_t m0 = (size_t)mblk * 64;

    const float* Ag = g_scratch + (m0 * 4 + lb) * 192;      // row stride 768 f
    const float* Bg = g_w2r + ((size_t)lb * 1024 + (size_t)nblk * 256) * 192;

    auto cpA = [&](int kc, int s) {
        const float* src = Ag + kc * 32;
        const uint32_t dst = sb + (uint32_t)(s * S2_STW) * 4;
#pragma unroll
        for (int i = 0; i < 2; i++) {
            int idx = i * 384 + tid;
            if (idx < 512) {
                int row = idx >> 3, c4 = idx & 7;
                CP16(dst + (uint32_t)(row * SSTR + c4 * 4) * 4, src + (size_t)row * 768 + c4 * 4);
            }
        }
    };
    auto cpB = [&](int kc, int s) {
        const float* src = Bg + kc * 32;
        const uint32_t dst = sb + (uint32_t)(s * S2_STW + S2_AW) * 4;
#pragma unroll
        for (int i = 0; i < 6; i++) {
            int idx = i * 384 + tid;
            if (idx < 2048) {
                int row = idx >> 3, c4 = idx & 7;
                CP16(dst + (uint32_t)(row * SSTR + c4 * 4) * 4, src + (size_t)row * 192 + c4 * 4);
            }
        }
    };

    // roles
    const int wm = (wid >> 2) & 1;
    const int sraw = wid & 3;
    const int slot = (wid < 8) ? (wm ? (sraw ^ 1) : sraw) : 0;
    const int offs_tab[4] = {0, 56, 104, 160};
    const int noff = offs_tab[slot];
    const bool wide = (slot == 0 || slot == 2);          // 56-col -> NI=7
    const int lr = lane >> 2, lc = lane & 3;
    const int fw = wid - 8, tr = lane >> 3, tc = lane & 7;

    float c[2][7][4];
    float cf[4][6];
#pragma unroll
    for (int mi = 0; mi < 2; mi++)
#pragma unroll
        for (int ni = 0; ni < 7; ni++)
#pragma unroll
            for (int e = 0; e < 4; e++) c[mi][ni][e] = 0.f;
#pragma unroll
    for (int j = 0; j < 4; j++)
#pragma unroll
        for (int i = 0; i < 6; i++) cf[j][i] = 0.f;

    cpA(0, 0); cpB(0, 0); CPCOMMIT();
    cpA(1, 1); cpB(1, 1); CPCOMMIT();

#pragma unroll 1
    for (int kc = 0; kc < 6; kc++) {
        if (kc + 2 < 6) {
            cpA(kc + 2, (kc + 2) & 3); cpB(kc + 2, (kc + 2) & 3); CPCOMMIT();
            CPWAIT(2);
        } else if (kc + 2 == 6) {
            CPWAIT(1);
        } else {
            CPWAIT(0);
        }
        __syncthreads();

        const uint32_t* As = smu + (kc & 3) * S2_STW;
        const uint32_t* Bs = As + S2_AW;

        if (wid < 8) {
            if (wide) s2_mma_chunk<7>(As, Bs, c, wm, noff, lr, lc);
            else      s2_mma_chunk<6>(As, Bs, c, wm, noff, lr, lc);
        } else {
            const float* Af = (const float*)As;
            const float* Bf = (const float*)Bs;
            const int r0 = 16 * fw + tr;
            const int n0 = 208 + tc;
#pragma unroll 4
            for (int k = 0; k < 32; k++) {
                float av[4], bv[6];
#pragma unroll
                for (int j = 0; j < 4; j++) av[j] = Af[(r0 + 4 * j) * SSTR + k];
#pragma unroll
                for (int i = 0; i < 6; i++) bv[i] = Bf[(n0 + 8 * i) * SSTR + k];
#pragma unroll
                for (int j = 0; j < 4; j++)
#pragma unroll
                    for (int i = 0; i < 6; i++) cf[j][i] += av[j] * bv[i];
            }
        }
    }

    const int gcolbase = lb * 1024 + nblk * 256;
    if (wid < 8) {
        if (wide) s2_mma_epi<7>(c, out, bias, m0, gcolbase, wm, noff, lr, lc);
        else      s2_mma_epi<6>(c, out, bias, m0, gcolbase, wm, noff, lr, lc);
    } else {
#pragma unroll
        for (int j = 0; j < 4; j++) {
            int row = 16 * fw + tr + 4 * j;
            float* orow = out + (m0 + row) * OUT_F + gcolbase;
#pragma unroll
            for (int i = 0; i < 6; i++) {
                int col = 208 + tc + 8 * i;
                orow[col] = cf[j][i] + __ldg(bias + gcolbase + col);
            }
        }
    }
}

// ---------------------------------------------------------------------------
extern "C" void kernel_launch(void* const* d_in, const int* in_sizes, int n_in,
                              void* d_out, int out_size)
{
    const float* x    = (const float*)d_in[0];
    const float* w1   = (const float*)d_in[1];
    const float* w2   = (const float*)d_in[2];
    const float* bias = (const float*)d_in[3];
    float* out = (float*)d_out;

    cudaFuncSetAttribute(s1_kernel, cudaFuncAttributeMaxDynamicSharedMemorySize, S1_SMEM);
    cudaFuncSetAttribute(s2_kernel, cudaFuncAttributeMaxDynamicSharedMemorySize, S2_SMEM);

    prep_kernel<<<384, 256>>>(w1, w2);
    // mblk fastest: per-kb / per-(lb,nblk) weight slices stay L2-hot
    s1_kernel<<<dim3(256, 4), 384, S1_SMEM>>>(x);
    s2_kernel<<<dim3(4, 256, 4), 384, S2_SMEM>>>(bias, out);
}

// round 14
// speedup vs baseline: 2.3067x; 2.3067x over previous
#include <cuda_runtime.h>
#include <cstdint>
#include <cstddef>

#define IN_F    4096
#define OUT_F   4096
#define BATCHSZ 16384
// stage1 per kb: M=16384, N=192, K=1024 ; stage2 per lb: M=16384, N=1024 (4x256), K=192

// scratch[(b*4 + l)*192 + kb*48 + b1], tf32-rounded fp32 (low 13 bits zero)
__device__ float g_scratch[(size_t)BATCHSZ * 4 * 192];
__device__ float g_w1r[4 * 192 * 1024];   // rna(tf32)-rounded weights
__device__ float g_w2r[4 * 1024 * 192];

#define SSTR 36   // padded row stride in 4B words (conflict-free, 16B aligned)

__device__ __forceinline__ uint32_t f2tf32(float f) {
    uint32_t r; asm("cvt.rna.tf32.f32 %0, %1;" : "=r"(r) : "f"(f)); return r;
}
#define CP16(dst, src) asm volatile("cp.async.cg.shared.global [%0], [%1], 16;" :: "r"(dst), "l"(src))
#define CPCOMMIT()     asm volatile("cp.async.commit_group;" ::: "memory")
#define CPWAIT(n)      asm volatile("cp.async.wait_group %0;" :: "n"(n) : "memory")

__device__ __forceinline__ uint32_t smem_u32(const void* p) {
    uint32_t a;
    asm("{ .reg .u64 t; cvta.to.shared.u64 t, %1; cvt.u32.u64 %0, t; }" : "=r"(a) : "l"(p));
    return a;
}

__device__ __forceinline__ void mma_tf32(float c[4], const uint32_t a[4], const uint32_t b[2]) {
    asm volatile(
        "mma.sync.aligned.m16n8k8.row.col.f32.tf32.tf32.f32 "
        "{%0,%1,%2,%3}, {%4,%5,%6,%7}, {%8,%9}, {%0,%1,%2,%3};"
        : "+f"(c[0]), "+f"(c[1]), "+f"(c[2]), "+f"(c[3])
        : "r"(a[0]), "r"(a[1]), "r"(a[2]), "r"(a[3]), "r"(b[0]), "r"(b[1]));
}

// ------------------------------------------------------------- prep
__global__ void prep_kernel(const float* __restrict__ w1, const float* __restrict__ w2) {
    const int n = 4 * 192 * 1024;   // == 4*1024*192
    for (int i = blockIdx.x * blockDim.x + threadIdx.x; i < n; i += gridDim.x * blockDim.x) {
        g_w1r[i] = __uint_as_float(f2tf32(w1[i]));
        g_w2r[i] = __uint_as_float(f2tf32(w2[i]));
    }
}

// ---------------------------------------------------------------------------
// Stage 1: CTA 64x192, K=1024 (32 chunks of 32). 256 thr, 8 warps = 2m x 4n,
// warp tile 32x48 (mi=2, ni=6). 4-stage cp.async ring, 1 sync/iter.
// Per stage (u32 words): A 64*36 = 2304 ; B 192*36 = 6912 ; total 9216 (36864B)
// ---------------------------------------------------------------------------
#define S1_STW   9216
#define S1_AW    2304
#define S1_SMEM  (4 * S1_STW * 4)    // 147456 B

__global__ void __launch_bounds__(256, 1)
s1_kernel(const float* __restrict__ x)
{
    extern __shared__ uint32_t smu[];
    const uint32_t sb = smem_u32(smu);
    const int tid = threadIdx.x, wid = tid >> 5, lane = tid & 31;
    const int wm = wid >> 2, wn = wid & 3;       // 2 x 4
    const int lr = lane >> 2, lc = lane & 3;
    const int mblk = blockIdx.x, kb = blockIdx.y;
    const size_t m0 = (size_t)mblk * 64;

    const float* xA = x + m0 * IN_F + (size_t)kb * 1024;
    const float* wB = g_w1r + (size_t)kb * 192 * 1024;

    auto cpA = [&](int kc, int s) {
        const float* src = xA + kc * 32;
        const uint32_t dst = sb + (uint32_t)(s * S1_STW) * 4;
#pragma unroll
        for (int i = 0; i < 2; i++) {
            int idx = i * 256 + tid, row = idx >> 3, c4 = idx & 7;
            CP16(dst + (uint32_t)(row * SSTR + c4 * 4) * 4, src + (size_t)row * IN_F + c4 * 4);
        }
    };
    auto cpB = [&](int kc, int s) {
        const float* src = wB + kc * 32;
        const uint32_t dst = sb + (uint32_t)(s * S1_STW + S1_AW) * 4;
#pragma unroll
        for (int i = 0; i < 6; i++) {
            int idx = i * 256 + tid, row = idx >> 3, c4 = idx & 7;
            CP16(dst + (uint32_t)(row * SSTR + c4 * 4) * 4, src + (size_t)row * 1024 + c4 * 4);
        }
    };

    float c[2][6][4];
#pragma unroll
    for (int mi = 0; mi < 2; mi++)
#pragma unroll
        for (int ni = 0; ni < 6; ni++)
#pragma unroll
            for (int e = 0; e < 4; e++) c[mi][ni][e] = 0.f;

    cpA(0, 0); cpB(0, 0); CPCOMMIT();
    cpA(1, 1); cpB(1, 1); CPCOMMIT();

#pragma unroll 1
    for (int kc = 0; kc < 32; kc++) {
        if (kc + 2 < 32) {
            cpA(kc + 2, (kc + 2) & 3); cpB(kc + 2, (kc + 2) & 3); CPCOMMIT();
            CPWAIT(2);
        } else if (kc + 2 == 32) {
            CPWAIT(1);
        } else {
            CPWAIT(0);
        }
        __syncthreads();

        const uint32_t* As = smu + (kc & 3) * S1_STW;
        const uint32_t* Bs = As + S1_AW;
#pragma unroll
        for (int kk = 0; kk < 4; kk++) {
            const int cc = kk * 8 + lc;
            uint32_t a[2][4], b[6][2];
#pragma unroll
            for (int mi = 0; mi < 2; mi++) {
                int r = wm * 32 + mi * 16 + lr;
                a[mi][0] = f2tf32(__uint_as_float(As[r * SSTR + cc]));
                a[mi][1] = f2tf32(__uint_as_float(As[(r + 8) * SSTR + cc]));
                a[mi][2] = f2tf32(__uint_as_float(As[r * SSTR + cc + 4]));
                a[mi][3] = f2tf32(__uint_as_float(As[(r + 8) * SSTR + cc + 4]));
            }
#pragma unroll
            for (int ni = 0; ni < 6; ni++) {
                int n = wn * 48 + ni * 8 + lr;
                b[ni][0] = Bs[n * SSTR + cc];        // pre-rounded, no cvt
                b[ni][1] = Bs[n * SSTR + cc + 4];
            }
#pragma unroll
            for (int mi = 0; mi < 2; mi++)
#pragma unroll
                for (int ni = 0; ni < 6; ni++)
                    mma_tf32(c[mi][ni], a[mi], b[ni]);
        }
    }

    // Epilogue: warp's 48-col span == one l block (l = wn). tf32-round, then
    // contiguous 192B-run writes with fused block transpose.
#pragma unroll
    for (int mi = 0; mi < 2; mi++) {
        int row0 = wm * 32 + mi * 16 + lr;
        size_t g0 = ((m0 + row0) * 4 + wn) * 192 + (size_t)kb * 48 + 2 * lc;
#pragma unroll
        for (int ni = 0; ni < 6; ni++) {
            float2 v0 = {__uint_as_float(f2tf32(c[mi][ni][0])),
                         __uint_as_float(f2tf32(c[mi][ni][1]))};
            float2 v1 = {__uint_as_float(f2tf32(c[mi][ni][2])),
                         __uint_as_float(f2tf32(c[mi][ni][3]))};
            *(float2*)(g_scratch + g0 + ni * 8) = v0;                        // row0
            *(float2*)(g_scratch + g0 + ni * 8 + (size_t)8 * 4 * 192) = v1;  // row0+8
        }
    }
}

// ---------------------------------------------------------------------------
// Stage 2: CTA 128x256, K=192 (6 chunks of 32). 256 thr, 8 warps = 2m x 4n,
// warp tile 64x64 (mi=4, ni=8). 4-stage ring, 1 sync/iter, zero cvt.
// Per stage (u32): A 128*36 = 4608 ; B 256*36 = 9216 ; total 13824 (55296B)
// ---------------------------------------------------------------------------
#define S2_STW   13824
#define S2_AW    4608
#define S2_SMEM  (4 * S2_STW * 4)    // 221184 B

__global__ void __launch_bounds__(256, 1)
s2_kernel(const float* __restrict__ bias, float* __restrict__ out)
{
    extern __shared__ uint32_t smu[];
    const uint32_t sb = smem_u32(smu);
    const int tid = threadIdx.x, wid = tid >> 5, lane = tid & 31;
    const int wm = wid >> 2, wn = wid & 3;       // 2 x 4
    const int lr = lane >> 2, lc = lane & 3;
    const int nblk = blockIdx.x, mblk = blockIdx.y, lb = blockIdx.z;
    const size_t m0 = (size_t)mblk * 128;

    const float* Ag = g_scratch + (m0 * 4 + lb) * 192;
    const float* Bg = g_w2r + ((size_t)lb * 1024 + (size_t)nblk * 256) * 192;

    auto cpA = [&](int kc, int s) {
        const float* src = Ag + kc * 32;
        const uint32_t dst = sb + (uint32_t)(s * S2_STW) * 4;
#pragma unroll
        for (int i = 0; i < 4; i++) {
            int idx = i * 256 + tid, row = idx >> 3, c4 = idx & 7;
            CP16(dst + (uint32_t)(row * SSTR + c4 * 4) * 4, src + (size_t)row * (4 * 192) + c4 * 4);
        }
    };
    auto cpB = [&](int kc, int s) {
        const float* src = Bg + kc * 32;
        const uint32_t dst = sb + (uint32_t)(s * S2_STW + S2_AW) * 4;
#pragma unroll
        for (int i = 0; i < 8; i++) {
            int idx = i * 256 + tid, row = idx >> 3, c4 = idx & 7;
            CP16(dst + (uint32_t)(row * SSTR + c4 * 4) * 4, src + (size_t)row * 192 + c4 * 4);
        }
    };

    float c[4][8][4];
#pragma unroll
    for (int mi = 0; mi < 4; mi++)
#pragma unroll
        for (int ni = 0; ni < 8; ni++)
#pragma unroll
            for (int e = 0; e < 4; e++) c[mi][ni][e] = 0.f;

    cpA(0, 0); cpB(0, 0); CPCOMMIT();
    cpA(1, 1); cpB(1, 1); CPCOMMIT();

#pragma unroll 1
    for (int kc = 0; kc < 6; kc++) {
        if (kc + 2 < 6) {
            cpA(kc + 2, (kc + 2) & 3); cpB(kc + 2, (kc + 2) & 3); CPCOMMIT();
            CPWAIT(2);
        } else if (kc + 2 == 6) {
            CPWAIT(1);
        } else {
            CPWAIT(0);
        }
        __syncthreads();

        const uint32_t* As = smu + (kc & 3) * S2_STW;
        const uint32_t* Bs = As + S2_AW;
#pragma unroll
        for (int kk = 0; kk < 4; kk++) {
            const int cc = kk * 8 + lc;
            uint32_t a[4][4], b[8][2];
#pragma unroll
            for (int mi = 0; mi < 4; mi++) {
                int r = wm * 64 + mi * 16 + lr;
                a[mi][0] = As[r * SSTR + cc];
                a[mi][1] = As[(r + 8) * SSTR + cc];
                a[mi][2] = As[r * SSTR + cc + 4];
                a[mi][3] = As[(r + 8) * SSTR + cc + 4];
            }
#pragma unroll
            for (int ni = 0; ni < 8; ni++) {
                int n = wn * 64 + ni * 8 + lr;
                b[ni][0] = Bs[n * SSTR + cc];
                b[ni][1] = Bs[n * SSTR + cc + 4];
            }
#pragma unroll
            for (int mi = 0; mi < 4; mi++)
#pragma unroll
                for (int ni = 0; ni < 8; ni++)
                    mma_tf32(c[mi][ni], a[mi], b[ni]);
        }
    }

    // Epilogue: bias preload, 128B-aligned float2 writes per row.
    const int col0 = lb * 1024 + nblk * 256 + wn * 64 + 2 * lc;
    float2 bs[8];
#pragma unroll
    for (int ni = 0; ni < 8; ni++)
        bs[ni] = *(const float2*)(bias + col0 + ni * 8);

#pragma unroll
    for (int mi = 0; mi < 4; mi++) {
        int row0 = wm * 64 + mi * 16 + lr;
        float* o0 = out + (m0 + row0) * OUT_F + col0;
#pragma unroll
        for (int ni = 0; ni < 8; ni++) {
            float2 v0 = {c[mi][ni][0] + bs[ni].x, c[mi][ni][1] + bs[ni].y};
            float2 v1 = {c[mi][ni][2] + bs[ni].x, c[mi][ni][3] + bs[ni].y};
            *(float2*)(o0 + ni * 8) = v0;
            *(float2*)(o0 + ni * 8 + (size_t)8 * OUT_F) = v1;
        }
    }
}

// ---------------------------------------------------------------------------
extern "C" void kernel_launch(void* const* d_in, const int* in_sizes, int n_in,
                              void* d_out, int out_size)
{
    const float* x    = (const float*)d_in[0];
    const float* w1   = (const float*)d_in[1];
    const float* w2   = (const float*)d_in[2];
    const float* bias = (const float*)d_in[3];
    float* out = (float*)d_out;

    cudaFuncSetAttribute(s1_kernel, cudaFuncAttributeMaxDynamicSharedMemorySize, S1_SMEM);
    cudaFuncSetAttribute(s2_kernel, cudaFuncAttributeMaxDynamicSharedMemorySize, S2_SMEM);

    prep_kernel<<<384, 256>>>(w1, w2);
    // mblk fastest: per-kb / per-(lb,nblk) weight slices stay L2-hot across the m-sweep
    s1_kernel<<<dim3(256, 4), 256, S1_SMEM>>>(x);
    s2_kernel<<<dim3(4, 128, 4), 256, S2_SMEM>>>(bias, out);
}